// round 8
// baseline (speedup 1.0000x reference)
#include <cuda_runtime.h>
#include <cuda_bf16.h>

#define H      2048
#define E      64
#define NTOK   16384
#define TM     64
#define NBLK   256
#define NKT    32

typedef unsigned int u32;

// -------- device scratch (allocation-free) --------
__device__ __align__(16) unsigned char g_Wh[NKT * 8192];
__device__ __align__(16) unsigned char g_Wm[NKT * 8192];
__device__ __align__(16) unsigned char g_Wl[NKT * 8192];
__device__ float g_part_load[NBLK * E];
__device__ float g_part_z[NBLK];
__device__ unsigned int g_arrive = 0;

#define SWZ(o) ((o) ^ (((o) >> 3) & 0x70))

// dynamic smem: 2 buffers x (3 A-splits 8KB + 3 B-splits 8KB) = 98304 B
#define BUF_SZ 49152
#define A_P(p) ((p) * 8192)
#define B_P(p) (24576 + (p) * 8192)
#define SMEM_DYN (2 * BUF_SZ)

__device__ __forceinline__ u32 smem_u32(const void* p) {
    u32 a;
    asm("{ .reg .u64 t; cvta.to.shared.u64 t, %1; cvt.u32.u64 %0, t; }" : "=r"(a) : "l"(p));
    return a;
}

#define CP16(dst, src) \
    asm volatile("cp.async.cg.shared.global [%0], [%1], 16;" :: "r"(dst), "l"(src) : "memory")
#define CP_COMMIT() asm volatile("cp.async.commit_group;" ::: "memory")
#define CP_WAIT0()  asm volatile("cp.async.wait_group 0;" ::: "memory")

#define LDSM4(r0, r1, r2, r3, addr) \
    asm volatile("ldmatrix.sync.aligned.m8n8.x4.shared.b16 {%0,%1,%2,%3}, [%4];" \
        : "=r"(r0), "=r"(r1), "=r"(r2), "=r"(r3) : "r"(addr))

#define MMA(d, a, b0, b1) \
    asm volatile("mma.sync.aligned.m16n8k16.row.col.f32.bf16.bf16.f32 " \
        "{%0,%1,%2,%3}, {%4,%5,%6,%7}, {%8,%9}, {%0,%1,%2,%3};" \
        : "+f"((d)[0]), "+f"((d)[1]), "+f"((d)[2]), "+f"((d)[3]) \
        : "r"((a)[0]), "r"((a)[1]), "r"((a)[2]), "r"((a)[3]), "r"(b0), "r"(b1))

// 3-way bf16 split of a float pair (residuals exact in fp32)
__device__ __forceinline__ void split3(float a, float b, u32& h, u32& m, u32& l) {
    __nv_bfloat162 hb = __floats2bfloat162_rn(a, b);
    float2 hf = __bfloat1622float2(hb);
    float ra = a - hf.x, rb = b - hf.y;
    __nv_bfloat162 mb = __floats2bfloat162_rn(ra, rb);
    float2 mf = __bfloat1622float2(mb);
    __nv_bfloat162 lb = __floats2bfloat162_rn(ra - mf.x, rb - mf.y);
    h = *(u32*)&hb; m = *(u32*)&mb; l = *(u32*)&lb;
}

// -------- prep: split + pre-swizzle W into per-tile bf16 arrays --------
__global__ __launch_bounds__(256) void prep_kernel(const float* __restrict__ W) {
    int e = blockIdx.x;
    int t = threadIdx.x;
    int k0 = t * 8;
    int kt = k0 >> 6;
    int c  = k0 & 63;
    const float4* src = (const float4*)(W + (size_t)e * H + k0);
    float4 a = src[0], b = src[1];
    uint4 Hv, Mv, Lv;
    split3(a.x, a.y, Hv.x, Mv.x, Lv.x);
    split3(a.z, a.w, Hv.y, Mv.y, Lv.y);
    split3(b.x, b.y, Hv.z, Mv.z, Lv.z);
    split3(b.z, b.w, Hv.w, Mv.w, Lv.w);
    u32 off = kt * 8192 + SWZ((u32)(e * 128 + c * 2));
    *(uint4*)(g_Wh + off) = Hv;
    *(uint4*)(g_Wm + off) = Mv;
    *(uint4*)(g_Wl + off) = Lv;
}

__device__ __forceinline__ void pass4(float (*acc)[4], const u32* a, const u32* b) {
    MMA(acc[0], a, b[0], b[1]); MMA(acc[1], a, b[2], b[3]);
    MMA(acc[2], a, b[4], b[5]); MMA(acc[3], a, b[6], b[7]);
}

// per-tile compute: warp = 16 tokens (group tg) x 32 experts (half ehalf)
__device__ __forceinline__ void compute_tile(
    u32 base, float (*acc)[4], int tg, int ehalf, int lane)
{
    const int arow = ((lane >> 3) & 1) * 8 + (lane & 7);
    const int acol = (lane >> 4) * 8;
    const int rowpart = ((lane >> 4) & 1) * 8 + (lane & 7);
    const int kb16 = ((lane >> 3) & 1) * 16;
    #pragma unroll
    for (int c = 0; c < 4; c++) {
        u32 ah[4], am[4], al[4];
        u32 aoff = SWZ((u32)((tg * 16 + arow) * 128 + (c * 16 + acol) * 2));
        LDSM4(ah[0], ah[1], ah[2], ah[3], base + A_P(0) + aoff);
        LDSM4(am[0], am[1], am[2], am[3], base + A_P(1) + aoff);
        LDSM4(al[0], al[1], al[2], al[3], base + A_P(2) + aoff);
        u32 bh[8], bm[8], bl[8];
        #pragma unroll
        for (int g = 0; g < 2; g++) {
            u32 boff = SWZ((u32)((ehalf * 32 + g * 16 + rowpart) * 128 + c * 32 + kb16));
            LDSM4(bh[4*g], bh[4*g+1], bh[4*g+2], bh[4*g+3], base + B_P(0) + boff);
            LDSM4(bm[4*g], bm[4*g+1], bm[4*g+2], bm[4*g+3], base + B_P(1) + boff);
            LDSM4(bl[4*g], bl[4*g+1], bl[4*g+2], bl[4*g+3], base + B_P(2) + boff);
        }
        pass4(acc, ah, bh); pass4(acc, am, bh); pass4(acc, ah, bm);
        pass4(acc, am, bm); pass4(acc, al, bh); pass4(acc, ah, bl);
    }
}

// stage pre-swizzled B splits for tile kt (24 KB)
__device__ __forceinline__ void stage_B(int kt, u32 smDst, int tid) {
    u32 d = smDst + tid * 32;
    const unsigned char* s;
    s = g_Wh + kt * 8192 + tid * 32; CP16(d + B_P(0) - 24576 + 24576, s); CP16(d + 24576 + 16, s + 16);
    s = g_Wm + kt * 8192 + tid * 32; CP16(d + 32768, s); CP16(d + 32768 + 16, s + 16);
    s = g_Wl + kt * 8192 + tid * 32; CP16(d + 40960, s); CP16(d + 40960 + 16, s + 16);
}

// split this thread's 16 x-floats and store 3 swizzled A tiles
__device__ __forceinline__ void convert_x(
    const float4* xr, unsigned char* bufp, int row, int c4)
{
    #pragma unroll
    for (int q = 0; q < 2; q++) {
        float4 v0 = xr[2 * q], v1 = xr[2 * q + 1];
        uint4 Hv, Mv, Lv;
        split3(v0.x, v0.y, Hv.x, Mv.x, Lv.x);
        split3(v0.z, v0.w, Hv.y, Mv.y, Lv.y);
        split3(v1.x, v1.y, Hv.z, Mv.z, Lv.z);
        split3(v1.z, v1.w, Hv.w, Mv.w, Lv.w);
        u32 sw = SWZ((u32)(row * 128 + c4 * 32 + q * 16));
        *(uint4*)(bufp + A_P(0) + sw) = Hv;
        *(uint4*)(bufp + A_P(1) + sw) = Mv;
        *(uint4*)(bufp + A_P(2) + sw) = Lv;
    }
}

__global__ __launch_bounds__(256, 2) void gate_kernel(
    const float* __restrict__ x, float* __restrict__ out, int out_size)
{
    extern __shared__ __align__(128) unsigned char smc[];
    __shared__ float zsm[TM];
    __shared__ float redsm[256];
    __shared__ float zred2[8];
    __shared__ unsigned int lastflag;

    const u32 smB = smem_u32(smc);
    const int tid = threadIdx.x;
    const int w = tid >> 5;
    const int lane = tid & 31;
    const int blk = blockIdx.x;
    const int rowBase = blk * TM;
    const int tg = w & 3;         // token group (16 tokens)
    const int ehalf = w >> 2;     // expert half (32 experts)

    const int xrow = tid >> 2;          // conversion: token row 0..63
    const int xc4  = tid & 3;           // k block of 16 floats

    float acc[4][4];
    #pragma unroll
    for (int n = 0; n < 4; n++)
        #pragma unroll
        for (int j = 0; j < 4; j++) acc[n][j] = 0.0f;

    // prologue: B tile 0 via cp.async, x tile 0 convert
    stage_B(0, smB, tid);
    CP_COMMIT();
    {
        float4 xr[4];
        const float4* src = (const float4*)(x + (size_t)(rowBase + xrow) * H + xc4 * 16);
        #pragma unroll
        for (int j = 0; j < 4; j++) xr[j] = src[j];
        convert_x(xr, smc, xrow, xc4);
    }
    CP_WAIT0();
    __syncthreads();

    for (int kt = 0; kt < NKT; kt++) {
        const int buf = kt & 1;
        const u32 base = smB + buf * BUF_SZ;
        float4 xr[4];
        if (kt + 1 < NKT) {
            stage_B(kt + 1, smB + (buf ^ 1) * BUF_SZ, tid);
            CP_COMMIT();
            const float4* src = (const float4*)(
                x + (size_t)(rowBase + xrow) * H + (kt + 1) * 64 + xc4 * 16);
            #pragma unroll
            for (int j = 0; j < 4; j++) xr[j] = src[j];
        }

        compute_tile(base, acc, tg, ehalf, lane);

        if (kt + 1 < NKT) {
            convert_x(xr, smc + (buf ^ 1) * BUF_SZ, xrow, xc4);
            CP_WAIT0();
        }
        __syncthreads();
    }

    // -------- epilogue: logits -> smem scores [64][68] (reuse buffer 0) --------
    float* sc = (float*)smc;
    const int r0 = tg * 16 + (lane >> 2);
    #pragma unroll
    for (int g = 0; g < 4; g++) {
        int e = ehalf * 32 + g * 8 + (lane & 3) * 2;
        *(float2*)(sc + r0 * 68 + e)       = make_float2(acc[g][0], acc[g][1]);
        *(float2*)(sc + (r0 + 8) * 68 + e) = make_float2(acc[g][2], acc[g][3]);
    }
    __syncthreads();

    if (tid < TM) {
        float* row = sc + tid * 68;
        float m1 = -1e30f, m2 = -1e30f; int i1 = 0, i2 = 0;
        #pragma unroll 8
        for (int e = 0; e < E; e++) {
            float v = row[e];
            if (v > m1) { m2 = m1; i2 = i1; m1 = v; i1 = e; }
            else if (v > m2) { m2 = v; i2 = e; }
        }
        float s = 0.0f;
        #pragma unroll 8
        for (int e = 0; e < E; e++) { float u = __expf(row[e] - m1); row[e] = u; s += u; }
        float inv = 1.0f / s;
        #pragma unroll 8
        for (int e = 0; e < E; e++) row[e] *= inv;   // normalized probs for lb loss
        float lse = m1 + __logf(s);
        zsm[tid] = lse * lse;

        // softmax over the top-2 PROBABILITIES (p1 = 1/S, p2 = exp(m2-m1)/S)
        float p1 = inv, p2 = __expf(m2 - m1) * inv;
        float r2 = 1.0f / (1.0f + __expf(p1 - p2));
        float r1 = 1.0f - r2;

        int gt = rowBase + tid;
        if (2 * gt + 1 < out_size) { out[2 * gt] = r1; out[2 * gt + 1] = r2; }
        int ib = 2 * NTOK;
        if (ib + 2 * gt + 1 < out_size) {
            out[ib + 2 * gt] = (float)i1; out[ib + 2 * gt + 1] = (float)i2;
        }
    }
    __syncthreads();

    if (tid < E) {
        float s = 0.0f;
        #pragma unroll 8
        for (int t = 0; t < TM; t++) s += sc[t * 68 + tid];
        g_part_load[blk * E + tid] = s;
    }
    if (tid == E) {
        float z = 0.0f;
        #pragma unroll 8
        for (int t = 0; t < TM; t++) z += zsm[t];
        g_part_z[blk] = z;
    }

    // -------- last-block loss reduction --------
    __threadfence();
    __syncthreads();
    if (tid == 0) {
        unsigned int v = atomicAdd(&g_arrive, 1u);
        lastflag = (v == NBLK - 1) ? 1u : 0u;
    }
    __syncthreads();
    if (lastflag) {
        __threadfence();
        int qq = tid >> 6, e = tid & 63;
        float sacc = 0.0f;
        for (int b = qq * 64; b < qq * 64 + 64; b++) sacc += g_part_load[b * E + e];
        redsm[tid] = sacc;
        __syncthreads();
        if (tid < E) {
            float S = redsm[tid] + redsm[64 + tid] + redsm[128 + tid] + redsm[192 + tid];
            float d = S * (1.0f / (float)NTOK) - (1.0f / (float)E);
            redsm[tid] = d * d;
        }
        __syncthreads();
        if (tid < 32) {
            float v = redsm[tid] + redsm[tid + 32];
            #pragma unroll
            for (int o = 16; o > 0; o >>= 1) v += __shfl_down_sync(0xFFFFFFFFu, v, o);
            if (tid == 0) redsm[0] = v;   // lb sum
        }
        {
            float zv = g_part_z[tid];     // NBLK == 256 == blockDim
            #pragma unroll
            for (int o = 16; o > 0; o >>= 1) zv += __shfl_down_sync(0xFFFFFFFFu, zv, o);
            if (lane == 0) zred2[w] = zv;
        }
        __syncthreads();
        if (tid == 0) {
            float z = 0.0f;
            #pragma unroll
            for (int ww = 0; ww < 8; ww++) z += zred2[ww];
            float total = 0.01f * redsm[0] + 1e-4f * (z / (float)NTOK);
            if (out_size > 4 * NTOK) out[4 * NTOK] = total;
            g_arrive = 0;
        }
    }
}

extern "C" void kernel_launch(void* const* d_in, const int* in_sizes, int n_in,
                              void* d_out, int out_size)
{
    const float* x = (const float*)d_in[0];
    const float* W = (const float*)d_in[1];
    float* out = (float*)d_out;

    cudaFuncSetAttribute(gate_kernel, cudaFuncAttributeMaxDynamicSharedMemorySize, SMEM_DYN);
    prep_kernel<<<E, 256>>>(W);
    gate_kernel<<<NBLK, 256, SMEM_DYN>>>(x, out, out_size);
}